// round 3
// baseline (speedup 1.0000x reference)
#include <cuda_runtime.h>
#include <math.h>

// Problem dims
#define SEQLEN 8192
#define INSZ   512
#define HSZ    2048
#define OSZ    512

// Recurrence: 128 CTAs x 16 rows; thread (sub=tid>>4, row=tid&15) owns
// W[cta*16+row][sub*128 .. +127] in registers.
#define NCTA 128
#define RPC  16

// Scratch (device globals: allocation-free rule)
__device__ float    g_A[(size_t)SEQLEN * HSZ];         // U x_t + U_b ; reused as Z
__device__ float    g_Hst[(size_t)(SEQLEN + 1) * HSZ]; // h_0 .. h_8192
__device__ unsigned g_flags[NCTA];                     // per-CTA published step

// ---------------------------------------------------------------------------
// PTX helpers
// ---------------------------------------------------------------------------
static __device__ __forceinline__ unsigned ld_acq(const unsigned* p) {
    unsigned v;
    asm volatile("ld.acquire.gpu.global.u32 %0, [%1];" : "=r"(v) : "l"(p));
    return v;
}
static __device__ __forceinline__ void st_rel(unsigned* p, unsigned v) {
    asm volatile("st.release.gpu.global.u32 [%0], %1;" :: "l"(p), "r"(v));
}
// packed f32x2 FMA: acc.{lo,hi} += a*b  (Blackwell; 2x fp32 rate)
static __device__ __forceinline__ void fma2(unsigned long long& acc,
                                            float a0, float a1, float b0, float b1) {
    asm("{\n\t"
        ".reg .b64 ta, tb;\n\t"
        "mov.b64 ta, {%1, %2};\n\t"
        "mov.b64 tb, {%3, %4};\n\t"
        "fma.rn.f32x2 %0, ta, tb, %0;\n\t"
        "}"
        : "+l"(acc) : "f"(a0), "f"(a1), "f"(b0), "f"(b1));
}
static __device__ __forceinline__ float unpack_sum(unsigned long long acc) {
    float lo, hi;
    asm("mov.b64 {%0, %1}, %2;" : "=f"(lo), "=f"(hi) : "l"(acc));
    return lo + hi;
}
// tanh(x) = 1 - 2/(e^{2x}+1) : MUFU ex2 + MUFU rcp, saturates correctly
static __device__ __forceinline__ float fast_tanh(float x) {
    float e = __expf(2.f * x);
    return 1.f - __fdividef(2.f, e + 1.f);
}

// ---------------------------------------------------------------------------
// Init: reset flags, load h_0
// ---------------------------------------------------------------------------
__global__ void init_k(const float* __restrict__ hidden) {
    int i = blockIdx.x * blockDim.x + threadIdx.x;
    if (i < NCTA) g_flags[i] = 0;
    if (i < HSZ)  g_Hst[i] = hidden[i];
}

// ---------------------------------------------------------------------------
// SGEMM: C[M,N] = A[M,K] * B[N,K]^T + bias[N]   (row-major)
// ---------------------------------------------------------------------------
__global__ __launch_bounds__(256) void sgemm_tn_bias(
    const float* __restrict__ A, const float* __restrict__ B,
    const float* __restrict__ bias, float* __restrict__ C,
    int M, int N, int K)
{
    __shared__ float As[8][128];
    __shared__ float Bs[8][128];
    const int tid  = threadIdx.x;
    const int tx   = tid & 15;
    const int ty   = tid >> 4;
    const int lrow = tid >> 1;
    const int lcol = (tid & 1) * 4;

    const float* Ap = A + (size_t)(blockIdx.y * 128 + lrow) * K + lcol;
    const float* Bp = B + (size_t)(blockIdx.x * 128 + lrow) * K + lcol;

    float acc[8][8];
    #pragma unroll
    for (int i = 0; i < 8; ++i)
        #pragma unroll
        for (int j = 0; j < 8; ++j) acc[i][j] = 0.f;

    for (int k0 = 0; k0 < K; k0 += 8) {
        float4 a4 = *(const float4*)(Ap + k0);
        float4 b4 = *(const float4*)(Bp + k0);
        As[lcol + 0][lrow] = a4.x; As[lcol + 1][lrow] = a4.y;
        As[lcol + 2][lrow] = a4.z; As[lcol + 3][lrow] = a4.w;
        Bs[lcol + 0][lrow] = b4.x; Bs[lcol + 1][lrow] = b4.y;
        Bs[lcol + 2][lrow] = b4.z; Bs[lcol + 3][lrow] = b4.w;
        __syncthreads();
        #pragma unroll
        for (int k = 0; k < 8; ++k) {
            float ar[8], br[8];
            *(float4*)&ar[0] = *(const float4*)&As[k][ty * 8];
            *(float4*)&ar[4] = *(const float4*)&As[k][ty * 8 + 4];
            *(float4*)&br[0] = *(const float4*)&Bs[k][tx * 8];
            *(float4*)&br[4] = *(const float4*)&Bs[k][tx * 8 + 4];
            #pragma unroll
            for (int i = 0; i < 8; ++i)
                #pragma unroll
                for (int j = 0; j < 8; ++j)
                    acc[i][j] = fmaf(ar[i], br[j], acc[i][j]);
        }
        __syncthreads();
    }

    const int cm = blockIdx.y * 128 + ty * 8;
    const int cn = blockIdx.x * 128 + tx * 8;
    float bv[8];
    #pragma unroll
    for (int j = 0; j < 8; ++j) bv[j] = bias[cn + j];
    #pragma unroll
    for (int i = 0; i < 8; ++i) {
        float4 o0, o1;
        o0.x = acc[i][0] + bv[0]; o0.y = acc[i][1] + bv[1];
        o0.z = acc[i][2] + bv[2]; o0.w = acc[i][3] + bv[3];
        o1.x = acc[i][4] + bv[4]; o1.y = acc[i][5] + bv[5];
        o1.z = acc[i][6] + bv[6]; o1.w = acc[i][7] + bv[7];
        *(float4*)(C + (size_t)(cm + i) * N + cn)     = o0;
        *(float4*)(C + (size_t)(cm + i) * N + cn + 4) = o1;
    }
}

// ---------------------------------------------------------------------------
// Persistent recurrence, W in registers, per-CTA release flags.
//   h_{i+1} = tanh(A[i] + W h_i + W_b)
// Per step: parallel flag poll (2 pollers/flag) -> bar -> broadcast h loads +
// packed FMA -> shfl -> smem (double-buffered) -> bar -> warp0 leaders reduce,
// fast-tanh, store h, release own flag. No atomics, no second full barrier.
// ---------------------------------------------------------------------------
__global__ __launch_bounds__(256, 1) void rnn_recur(
    const float* __restrict__ W, const float* __restrict__ Wb)
{
    const int tid = threadIdx.x;
    const int cta = blockIdx.x;
    const int sub = tid >> 4;     // 0..15  k-segment
    const int row = tid & 15;     // 0..15  local row
    const int grow = cta * RPC + row;

    // This thread's W slice in registers: W[grow][sub*128 .. +127]
    float4 wreg[32];
    {
        const float4* Wg = (const float4*)(W + (size_t)grow * HSZ) + sub * 32;
        #pragma unroll
        for (int j = 0; j < 32; ++j) wreg[j] = Wg[j];
    }
    const float wb = (tid < RPC) ? Wb[cta * RPC + tid] : 0.f;

    __shared__ __align__(16) float red_s[2][16][8];   // [parity][row][warp]
    __syncthreads();

    for (int i = 0; i < SEQLEN; ++i) {
        // Prefetch A[i] (flag-independent): hides DRAM latency under the wait
        float a_val = 0.f;
        if (tid < RPC) a_val = g_A[(size_t)i * HSZ + cta * RPC + tid];

        // Parallel wait: thread t polls flag[t&127]; 2 pollers per flag.
        if (i > 0) {
            const unsigned tgt = (unsigned)i;
            const unsigned* fp = &g_flags[tid & (NCTA - 1)];
            while (ld_acq(fp) < tgt) { }
        }
        __syncthreads();   // all flags >= i  ->  h_i fully published

        // Dot product over this thread's 128-wide k segment (broadcast loads)
        const float4* hp = (const float4*)(g_Hst + (size_t)i * HSZ) + sub * 32;
        unsigned long long acc0 = 0ull, acc1 = 0ull;
        #pragma unroll
        for (int j = 0; j < 32; ++j) {
            float4 h4 = hp[j];
            float4 w4 = wreg[j];
            fma2(acc0, h4.x, h4.y, w4.x, w4.y);
            fma2(acc1, h4.z, h4.w, w4.z, w4.w);
        }
        float part = unpack_sum(acc0) + unpack_sum(acc1);

        // Combine the two subs in this warp (lane r & r+16 hold same row)
        part += __shfl_down_sync(0xffffffffu, part, 16);
        if ((tid & 31) < 16) red_s[i & 1][tid & 15][tid >> 5] = part;
        __syncthreads();

        // Warp-0 leaders finish: 8-way add, tanh, store h, release flag
        if (tid < RPC) {
            const float* rs = &red_s[i & 1][tid][0];
            float4 u = *(const float4*)rs;
            float4 v = *(const float4*)(rs + 4);
            float s = ((u.x + u.y) + (u.z + u.w)) + ((v.x + v.y) + (v.z + v.w));
            float hv = fast_tanh(s + a_val + wb);
            g_Hst[(size_t)(i + 1) * HSZ + cta * RPC + tid] = hv;
            __syncwarp(0x0000ffffu);          // order h stores before release
            if (tid == 0) st_rel(&g_flags[cta], (unsigned)(i + 1));
        }
        // No second barrier: red_s is double-buffered; non-leader warps run
        // ahead to the next step's poll.
    }
}

// ---------------------------------------------------------------------------
// log_softmax over rows of Z [SEQLEN, OSZ], one warp per row
// ---------------------------------------------------------------------------
__global__ __launch_bounds__(128) void logsoftmax_k(
    const float* __restrict__ Z, float* __restrict__ Y)
{
    int warp = (blockIdx.x * blockDim.x + threadIdx.x) >> 5;
    int lane = threadIdx.x & 31;
    if (warp >= SEQLEN) return;
    const float* z = Z + (size_t)warp * OSZ;
    float v[16];
    float m = -INFINITY;
    #pragma unroll
    for (int j = 0; j < 16; ++j) {
        v[j] = z[lane + 32 * j];
        m = fmaxf(m, v[j]);
    }
    #pragma unroll
    for (int o = 16; o > 0; o >>= 1) m = fmaxf(m, __shfl_xor_sync(~0u, m, o));
    float s = 0.f;
    #pragma unroll
    for (int j = 0; j < 16; ++j) s += __expf(v[j] - m);
    #pragma unroll
    for (int o = 16; o > 0; o >>= 1) s += __shfl_xor_sync(~0u, s, o);
    float lse = m + __logf(s);
    float* y = Y + (size_t)warp * OSZ;
    #pragma unroll
    for (int j = 0; j < 16; ++j) y[lane + 32 * j] = v[j] - lse;
}

__global__ void copy_hfinal(float* __restrict__ out) {
    int i = blockIdx.x * blockDim.x + threadIdx.x;
    if (i < HSZ) out[i] = g_Hst[(size_t)SEQLEN * HSZ + i];
}

// ---------------------------------------------------------------------------
// kernel_launch
// Inputs: 0 input[8192,512] 1 hidden[1,2048] 2 U_w[2048,512] 3 U_b[2048]
//         4 W_w[2048,2048]  5 W_b[2048]      6 V_w[512,2048]  7 V_b[512]
// Output: y[8192,512] ++ h_final[2048]
// ---------------------------------------------------------------------------
extern "C" void kernel_launch(void* const* d_in, const int* in_sizes, int n_in,
                              void* d_out, int out_size)
{
    (void)in_sizes; (void)n_in; (void)out_size;
    const float* input  = (const float*)d_in[0];
    const float* hidden = (const float*)d_in[1];
    const float* U_w    = (const float*)d_in[2];
    const float* U_b    = (const float*)d_in[3];
    const float* W_w    = (const float*)d_in[4];
    const float* W_b    = (const float*)d_in[5];
    const float* V_w    = (const float*)d_in[6];
    const float* V_b    = (const float*)d_in[7];
    float* out = (float*)d_out;

    float *pA, *pH;
    cudaGetSymbolAddress((void**)&pA, g_A);
    cudaGetSymbolAddress((void**)&pH, g_Hst);

    // 1) reset flags + h_0
    init_k<<<8, 256>>>(hidden);

    // 2) A = X U^T + U_b : [8192,2048]
    sgemm_tn_bias<<<dim3(HSZ / 128, SEQLEN / 128), 256>>>(
        input, U_w, U_b, pA, SEQLEN, HSZ, INSZ);

    // 3) sequential recurrence -> g_Hst rows 1..8192
    rnn_recur<<<NCTA, 256>>>(W_w, W_b);

    // 4) Z = H V^T + V_b : [8192,512]  (reuse g_A as Z; H rows 1..8192)
    sgemm_tn_bias<<<dim3(OSZ / 128, SEQLEN / 128), 256>>>(
        pH + HSZ, V_w, V_b, pA, SEQLEN, OSZ, HSZ);

    // 5) y = log_softmax(Z) ; h_final
    logsoftmax_k<<<SEQLEN / 4, 128>>>(pA, out);
    copy_hfinal<<<8, 256>>>(out + (size_t)SEQLEN * OSZ);
}

// round 4
// speedup vs baseline: 1.6480x; 1.6480x over previous
#include <cuda_runtime.h>
#include <math.h>

// Problem dims
#define SEQLEN 8192
#define INSZ   512
#define HSZ    2048
#define OSZ    512

// Recurrence: 128 CTAs x 16 rows; thread (sub=tid>>4, row=tid&15) owns
// W[cta*16+row][sub*128 .. +127] in registers.
#define NCTA 128
#define RPC  16

// Scratch (device globals: allocation-free rule)
__device__ float g_A[(size_t)SEQLEN * HSZ];         // U x_t + U_b ; reused as Z
__device__ float g_Hst[(size_t)(SEQLEN + 1) * HSZ]; // h_0 .. h_8192

// ---------------------------------------------------------------------------
// PTX helpers
// ---------------------------------------------------------------------------
// volatile float4 load: always L2-fresh, element-wise 4B atomic
static __device__ __forceinline__ float4 vld4(const float4* p) {
    float4 v;
    asm volatile("ld.volatile.global.v4.f32 {%0,%1,%2,%3}, [%4];"
                 : "=f"(v.x), "=f"(v.y), "=f"(v.z), "=f"(v.w) : "l"(p));
    return v;
}
// packed f32x2 FMA: acc.{lo,hi} += a*b  (Blackwell; 2x fp32 rate)
static __device__ __forceinline__ void fma2(unsigned long long& acc,
                                            float a0, float a1, float b0, float b1) {
    asm("{\n\t"
        ".reg .b64 ta, tb;\n\t"
        "mov.b64 ta, {%1, %2};\n\t"
        "mov.b64 tb, {%3, %4};\n\t"
        "fma.rn.f32x2 %0, ta, tb, %0;\n\t"
        "}"
        : "+l"(acc) : "f"(a0), "f"(a1), "f"(b0), "f"(b1));
}
static __device__ __forceinline__ float unpack_sum(unsigned long long acc) {
    float lo, hi;
    asm("mov.b64 {%0, %1}, %2;" : "=f"(lo), "=f"(hi) : "l"(acc));
    return lo + hi;
}
// tanh(x) = 1 - 2/(e^{2x}+1) : MUFU ex2 + approx div (validated: rel_err 1.1e-6)
static __device__ __forceinline__ float fast_tanh(float x) {
    float e = __expf(2.f * x);
    return 1.f - __fdividef(2.f, e + 1.f);
}

// ---------------------------------------------------------------------------
// Init: load h_0
// ---------------------------------------------------------------------------
__global__ void init_k(const float* __restrict__ hidden) {
    int i = blockIdx.x * blockDim.x + threadIdx.x;
    if (i < HSZ) g_Hst[i] = hidden[i];
}

// Poison rows 1..SEQLEN of g_Hst with NaN (dataflow sentinel).
// SEQLEN*HSZ/4 = 4M float4 -> 16384 blocks x 256 threads.
__global__ void poison_k() {
    size_t idx = (size_t)blockIdx.x * blockDim.x + threadIdx.x;
    const float qnan = __int_as_float(0x7fc00000);
    ((float4*)(g_Hst + HSZ))[idx] = make_float4(qnan, qnan, qnan, qnan);
}

// ---------------------------------------------------------------------------
// SGEMM: C[M,N] = A[M,K] * B[N,K]^T + bias[N]   (row-major)
// ---------------------------------------------------------------------------
__global__ __launch_bounds__(256) void sgemm_tn_bias(
    const float* __restrict__ A, const float* __restrict__ B,
    const float* __restrict__ bias, float* __restrict__ C,
    int M, int N, int K)
{
    __shared__ float As[8][128];
    __shared__ float Bs[8][128];
    const int tid  = threadIdx.x;
    const int tx   = tid & 15;
    const int ty   = tid >> 4;
    const int lrow = tid >> 1;
    const int lcol = (tid & 1) * 4;

    const float* Ap = A + (size_t)(blockIdx.y * 128 + lrow) * K + lcol;
    const float* Bp = B + (size_t)(blockIdx.x * 128 + lrow) * K + lcol;

    float acc[8][8];
    #pragma unroll
    for (int i = 0; i < 8; ++i)
        #pragma unroll
        for (int j = 0; j < 8; ++j) acc[i][j] = 0.f;

    for (int k0 = 0; k0 < K; k0 += 8) {
        float4 a4 = *(const float4*)(Ap + k0);
        float4 b4 = *(const float4*)(Bp + k0);
        As[lcol + 0][lrow] = a4.x; As[lcol + 1][lrow] = a4.y;
        As[lcol + 2][lrow] = a4.z; As[lcol + 3][lrow] = a4.w;
        Bs[lcol + 0][lrow] = b4.x; Bs[lcol + 1][lrow] = b4.y;
        Bs[lcol + 2][lrow] = b4.z; Bs[lcol + 3][lrow] = b4.w;
        __syncthreads();
        #pragma unroll
        for (int k = 0; k < 8; ++k) {
            float ar[8], br[8];
            *(float4*)&ar[0] = *(const float4*)&As[k][ty * 8];
            *(float4*)&ar[4] = *(const float4*)&As[k][ty * 8 + 4];
            *(float4*)&br[0] = *(const float4*)&Bs[k][tx * 8];
            *(float4*)&br[4] = *(const float4*)&Bs[k][tx * 8 + 4];
            #pragma unroll
            for (int i = 0; i < 8; ++i)
                #pragma unroll
                for (int j = 0; j < 8; ++j)
                    acc[i][j] = fmaf(ar[i], br[j], acc[i][j]);
        }
        __syncthreads();
    }

    const int cm = blockIdx.y * 128 + ty * 8;
    const int cn = blockIdx.x * 128 + tx * 8;
    float bv[8];
    #pragma unroll
    for (int j = 0; j < 8; ++j) bv[j] = bias[cn + j];
    #pragma unroll
    for (int i = 0; i < 8; ++i) {
        float4 o0, o1;
        o0.x = acc[i][0] + bv[0]; o0.y = acc[i][1] + bv[1];
        o0.z = acc[i][2] + bv[2]; o0.w = acc[i][3] + bv[3];
        o1.x = acc[i][4] + bv[4]; o1.y = acc[i][5] + bv[5];
        o1.z = acc[i][6] + bv[6]; o1.w = acc[i][7] + bv[7];
        *(float4*)(C + (size_t)(cm + i) * N + cn)     = o0;
        *(float4*)(C + (size_t)(cm + i) * N + cn + 4) = o1;
    }
}

// ---------------------------------------------------------------------------
// Persistent recurrence, W in registers, SENTINEL-IN-DATA sync.
//   h_{i+1} = tanh(A[i] + W h_i + W_b)
// No flags, no acquire/release: consumers ld.volatile h values and spin until
// non-NaN (poison). Poll traffic == data traffic, spread across 8KB/CTA.
// One __syncthreads per step (partials -> leaders), red_s double-buffered.
// ---------------------------------------------------------------------------
__global__ __launch_bounds__(256, 1) void rnn_recur(
    const float* __restrict__ W, const float* __restrict__ Wb)
{
    const int tid = threadIdx.x;
    const int cta = blockIdx.x;
    const int sub = tid >> 4;     // 0..15  k-segment
    const int row = tid & 15;     // 0..15  local row
    const int grow = cta * RPC + row;

    // This thread's W slice in registers: W[grow][sub*128 .. +127]
    float4 wreg[32];
    {
        const float4* Wg = (const float4*)(W + (size_t)grow * HSZ) + sub * 32;
        #pragma unroll
        for (int j = 0; j < 32; ++j) wreg[j] = Wg[j];
    }
    const float wb = (tid < RPC) ? Wb[cta * RPC + tid] : 0.f;

    __shared__ __align__(16) float red_s[2][16][8];   // [parity][row][warp]
    __syncthreads();

    for (int i = 0; i < SEQLEN; ++i) {
        // Prefetch A[i] (independent of h availability)
        float a_val = 0.f;
        if (tid < RPC) a_val = g_A[(size_t)i * HSZ + cta * RPC + tid];

        // Dot product over this thread's 128-wide k segment.
        // Chunked prefetch (MLP=8) + per-float4 NaN validity spin.
        const float4* hp = (const float4*)(g_Hst + (size_t)i * HSZ) + sub * 32;
        unsigned long long acc0 = 0ull, acc1 = 0ull;
        #pragma unroll
        for (int c = 0; c < 4; ++c) {
            float4 hb[8];
            #pragma unroll
            for (int j = 0; j < 8; ++j) hb[j] = vld4(hp + c * 8 + j);
            #pragma unroll
            for (int j = 0; j < 8; ++j) {
                float chk = (hb[j].x + hb[j].y) + (hb[j].z + hb[j].w);
                while (chk != chk) {   // NaN -> not yet published
                    hb[j] = vld4(hp + c * 8 + j);
                    chk = (hb[j].x + hb[j].y) + (hb[j].z + hb[j].w);
                }
                float4 w4 = wreg[c * 8 + j];
                fma2(acc0, hb[j].x, hb[j].y, w4.x, w4.y);
                fma2(acc1, hb[j].z, hb[j].w, w4.z, w4.w);
            }
        }
        float part = unpack_sum(acc0) + unpack_sum(acc1);

        // Combine the two subs in this warp (lane r & r+16 hold same row)
        part += __shfl_down_sync(0xffffffffu, part, 16);
        if ((tid & 31) < 16) red_s[i & 1][tid & 15][tid >> 5] = part;
        __syncthreads();

        // Warp-0 leaders: 8-way add, tanh, publish h_{i+1} (plain STG; the
        // NaN check on the consumer side is the synchronization).
        if (tid < RPC) {
            const float* rs = &red_s[i & 1][tid][0];
            float4 u = *(const float4*)rs;
            float4 v = *(const float4*)(rs + 4);
            float s = ((u.x + u.y) + (u.z + u.w)) + ((v.x + v.y) + (v.z + v.w));
            float hv = fast_tanh(s + a_val + wb);
            g_Hst[(size_t)(i + 1) * HSZ + cta * RPC + tid] = hv;
        }
        // Non-leader warps run ahead; their next-step volatile polls
        // self-synchronize. red_s parity keeps the reduce race-free.
    }
}

// ---------------------------------------------------------------------------
// log_softmax over rows of Z [SEQLEN, OSZ], one warp per row
// ---------------------------------------------------------------------------
__global__ __launch_bounds__(128) void logsoftmax_k(
    const float* __restrict__ Z, float* __restrict__ Y)
{
    int warp = (blockIdx.x * blockDim.x + threadIdx.x) >> 5;
    int lane = threadIdx.x & 31;
    if (warp >= SEQLEN) return;
    const float* z = Z + (size_t)warp * OSZ;
    float v[16];
    float m = -INFINITY;
    #pragma unroll
    for (int j = 0; j < 16; ++j) {
        v[j] = z[lane + 32 * j];
        m = fmaxf(m, v[j]);
    }
    #pragma unroll
    for (int o = 16; o > 0; o >>= 1) m = fmaxf(m, __shfl_xor_sync(~0u, m, o));
    float s = 0.f;
    #pragma unroll
    for (int j = 0; j < 16; ++j) s += __expf(v[j] - m);
    #pragma unroll
    for (int o = 16; o > 0; o >>= 1) s += __shfl_xor_sync(~0u, s, o);
    float lse = m + __logf(s);
    float* y = Y + (size_t)warp * OSZ;
    #pragma unroll
    for (int j = 0; j < 16; ++j) y[lane + 32 * j] = v[j] - lse;
}

__global__ void copy_hfinal(float* __restrict__ out) {
    int i = blockIdx.x * blockDim.x + threadIdx.x;
    if (i < HSZ) out[i] = g_Hst[(size_t)SEQLEN * HSZ + i];
}

// ---------------------------------------------------------------------------
// kernel_launch
// Inputs: 0 input[8192,512] 1 hidden[1,2048] 2 U_w[2048,512] 3 U_b[2048]
//         4 W_w[2048,2048]  5 W_b[2048]      6 V_w[512,2048]  7 V_b[512]
// Output: y[8192,512] ++ h_final[2048]
// ---------------------------------------------------------------------------
extern "C" void kernel_launch(void* const* d_in, const int* in_sizes, int n_in,
                              void* d_out, int out_size)
{
    (void)in_sizes; (void)n_in; (void)out_size;
    const float* input  = (const float*)d_in[0];
    const float* hidden = (const float*)d_in[1];
    const float* U_w    = (const float*)d_in[2];
    const float* U_b    = (const float*)d_in[3];
    const float* W_w    = (const float*)d_in[4];
    const float* W_b    = (const float*)d_in[5];
    const float* V_w    = (const float*)d_in[6];
    const float* V_b    = (const float*)d_in[7];
    float* out = (float*)d_out;

    float *pA, *pH;
    cudaGetSymbolAddress((void**)&pA, g_A);
    cudaGetSymbolAddress((void**)&pH, g_Hst);

    // 1) h_0 + poison rows 1..SEQLEN with NaN sentinel
    init_k<<<8, 256>>>(hidden);
    poison_k<<<(SEQLEN * HSZ / 4) / 256, 256>>>();

    // 2) A = X U^T + U_b : [8192,2048]
    sgemm_tn_bias<<<dim3(HSZ / 128, SEQLEN / 128), 256>>>(
        input, U_w, U_b, pA, SEQLEN, HSZ, INSZ);

    // 3) sequential recurrence -> g_Hst rows 1..8192
    rnn_recur<<<NCTA, 256>>>(W_w, W_b);

    // 4) Z = H V^T + V_b : [8192,512]  (reuse g_A as Z; H rows 1..8192)
    sgemm_tn_bias<<<dim3(OSZ / 128, SEQLEN / 128), 256>>>(
        pH + HSZ, V_w, V_b, pA, SEQLEN, OSZ, HSZ);

    // 5) y = log_softmax(Z) ; h_final
    logsoftmax_k<<<SEQLEN / 4, 128>>>(pA, out);
    copy_hfinal<<<8, 256>>>(out + (size_t)SEQLEN * OSZ);
}

// round 7
// speedup vs baseline: 2.5480x; 1.5461x over previous
#include <cuda_runtime.h>
#include <math.h>

// Problem dims
#define SEQLEN 8192
#define INSZ   512
#define HSZ    2048
#define OSZ    512

// Recurrence: 128 CTAs x 16 rows; thread (sub=tid>>4, row=tid&15) owns
// W[cta*16+row][sub*128 .. +127] in registers.
#define NCTA 128
#define RPC  16
#define FPAD 32   // flag padding: 32 u32 = 128B, one L2 line per flag

// Scratch (device globals: allocation-free rule)
__device__ float    g_A[(size_t)SEQLEN * HSZ];         // U x_t + U_b ; reused as Z
__device__ float    g_Hst[(size_t)(SEQLEN + 1) * HSZ]; // h_0 .. h_8192
__device__ unsigned g_flags[NCTA * FPAD];              // per-CTA step, 128B apart

// ---------------------------------------------------------------------------
// PTX helpers
// ---------------------------------------------------------------------------
static __device__ __forceinline__ unsigned ld_acq(const unsigned* p) {
    unsigned v;
    asm volatile("ld.acquire.gpu.global.u32 %0, [%1];" : "=r"(v) : "l"(p));
    return v;
}
static __device__ __forceinline__ void st_rel(unsigned* p, unsigned v) {
    asm volatile("st.release.gpu.global.u32 [%0], %1;" :: "l"(p), "r"(v));
}
// packed f32x2 FMA: acc.{lo,hi} += a*b  (Blackwell; 2x fp32 rate)
static __device__ __forceinline__ void fma2(unsigned long long& acc,
                                            float a0, float a1, float b0, float b1) {
    asm("{\n\t"
        ".reg .b64 ta, tb;\n\t"
        "mov.b64 ta, {%1, %2};\n\t"
        "mov.b64 tb, {%3, %4};\n\t"
        "fma.rn.f32x2 %0, ta, tb, %0;\n\t"
        "}"
        : "+l"(acc) : "f"(a0), "f"(a1), "f"(b0), "f"(b1));
}
static __device__ __forceinline__ float unpack_sum(unsigned long long acc) {
    float lo, hi;
    asm("mov.b64 {%0, %1}, %2;" : "=f"(lo), "=f"(hi) : "l"(acc));
    return lo + hi;
}
// tanh(x) = 1 - 2/(e^{2x}+1): MUFU ex2 + approx div (validated rel_err 1.1e-6)
static __device__ __forceinline__ float fast_tanh(float x) {
    float e = __expf(2.f * x);
    return 1.f - __fdividef(2.f, e + 1.f);
}

// ---------------------------------------------------------------------------
// Init: reset flags, load h_0
// ---------------------------------------------------------------------------
__global__ void init_k(const float* __restrict__ hidden) {
    int i = blockIdx.x * blockDim.x + threadIdx.x;
    if (i < NCTA * FPAD) g_flags[i] = 0;
    if (i < HSZ)         g_Hst[i] = hidden[i];
}

// ---------------------------------------------------------------------------
// SGEMM: C[M,N] = A[M,K] * B[N,K]^T + bias[N]   (row-major)
// ---------------------------------------------------------------------------
__global__ __launch_bounds__(256) void sgemm_tn_bias(
    const float* __restrict__ A, const float* __restrict__ B,
    const float* __restrict__ bias, float* __restrict__ C,
    int M, int N, int K)
{
    __shared__ float As[8][128];
    __shared__ float Bs[8][128];
    const int tid  = threadIdx.x;
    const int tx   = tid & 15;
    const int ty   = tid >> 4;
    const int lrow = tid >> 1;
    const int lcol = (tid & 1) * 4;

    const float* Ap = A + (size_t)(blockIdx.y * 128 + lrow) * K + lcol;
    const float* Bp = B + (size_t)(blockIdx.x * 128 + lrow) * K + lcol;

    float acc[8][8];
    #pragma unroll
    for (int i = 0; i < 8; ++i)
        #pragma unroll
        for (int j = 0; j < 8; ++j) acc[i][j] = 0.f;

    for (int k0 = 0; k0 < K; k0 += 8) {
        float4 a4 = *(const float4*)(Ap + k0);
        float4 b4 = *(const float4*)(Bp + k0);
        As[lcol + 0][lrow] = a4.x; As[lcol + 1][lrow] = a4.y;
        As[lcol + 2][lrow] = a4.z; As[lcol + 3][lrow] = a4.w;
        Bs[lcol + 0][lrow] = b4.x; Bs[lcol + 1][lrow] = b4.y;
        Bs[lcol + 2][lrow] = b4.z; Bs[lcol + 3][lrow] = b4.w;
        __syncthreads();
        #pragma unroll
        for (int k = 0; k < 8; ++k) {
            float ar[8], br[8];
            *(float4*)&ar[0] = *(const float4*)&As[k][ty * 8];
            *(float4*)&ar[4] = *(const float4*)&As[k][ty * 8 + 4];
            *(float4*)&br[0] = *(const float4*)&Bs[k][tx * 8];
            *(float4*)&br[4] = *(const float4*)&Bs[k][tx * 8 + 4];
            #pragma unroll
            for (int i = 0; i < 8; ++i)
                #pragma unroll
                for (int j = 0; j < 8; ++j)
                    acc[i][j] = fmaf(ar[i], br[j], acc[i][j]);
        }
        __syncthreads();
    }

    const int cm = blockIdx.y * 128 + ty * 8;
    const int cn = blockIdx.x * 128 + tx * 8;
    float bv[8];
    #pragma unroll
    for (int j = 0; j < 8; ++j) bv[j] = bias[cn + j];
    #pragma unroll
    for (int i = 0; i < 8; ++i) {
        float4 o0, o1;
        o0.x = acc[i][0] + bv[0]; o0.y = acc[i][1] + bv[1];
        o0.z = acc[i][2] + bv[2]; o0.w = acc[i][3] + bv[3];
        o1.x = acc[i][4] + bv[4]; o1.y = acc[i][5] + bv[5];
        o1.z = acc[i][6] + bv[6]; o1.w = acc[i][7] + bv[7];
        *(float4*)(C + (size_t)(cm + i) * N + cn)     = o0;
        *(float4*)(C + (size_t)(cm + i) * N + cn + 4) = o1;
    }
}

// ---------------------------------------------------------------------------
// Persistent recurrence, W in registers, padded per-CTA release flags.
//   h_{i+1} = tanh(A[i] + W h_i + W_b)
// R2-proven loop structure (closed by a trailing full barrier each step);
// only the sync PRIMITIVE differs from R2: 128 parallel per-CTA flag
// releases (each flag on its own 128B L2 line) instead of a single-address
// atomic counter, killing the LTS atomic-ALU funnel. 128 pollers grid-wide
// per flag line, 1 dependent ld.acquire each — proven-safe poll pressure.
// ---------------------------------------------------------------------------
__global__ __launch_bounds__(256, 1) void rnn_recur(
    const float* __restrict__ W, const float* __restrict__ Wb)
{
    const int tid = threadIdx.x;
    const int cta = blockIdx.x;
    const int sub = tid >> 4;     // 0..15  k-segment
    const int row = tid & 15;     // 0..15  local row
    const int grow = cta * RPC + row;

    // This thread's W slice in registers: W[grow][sub*128 .. +127]
    float4 wreg[32];
    {
        const float4* Wg = (const float4*)(W + (size_t)grow * HSZ) + sub * 32;
        #pragma unroll
        for (int j = 0; j < 32; ++j) wreg[j] = Wg[j];
    }
    const float wb = (tid < RPC) ? Wb[cta * RPC + tid] : 0.f;

    __shared__ __align__(16) float red_s[16][8];   // [row][warp]
    __syncthreads();

    for (int i = 0; i < SEQLEN; ++i) {
        // Prefetch A[i] (flag-independent) — hides DRAM latency under the wait
        float a_val = 0.f;
        if (tid < RPC) a_val = g_A[(size_t)i * HSZ + cta * RPC + tid];

        // Wait: thread t (t<128) polls CTA t's flag; each flag owns a line.
        if (i > 0) {
            if (tid < NCTA) {
                const unsigned* fp = &g_flags[tid * FPAD];
                while (ld_acq(fp) < (unsigned)i) { }
            }
            __syncthreads();   // all flags >= i  ->  h_i fully published
        }

        // Dot product over this thread's 128-wide k segment (broadcast loads)
        const float4* hp = (const float4*)(g_Hst + (size_t)i * HSZ) + sub * 32;
        unsigned long long acc0 = 0ull, acc1 = 0ull;
        #pragma unroll
        for (int j = 0; j < 32; ++j) {
            float4 h4 = hp[j];
            float4 w4 = wreg[j];
            fma2(acc0, h4.x, h4.y, w4.x, w4.y);
            fma2(acc1, h4.z, h4.w, w4.z, w4.w);
        }
        float part = unpack_sum(acc0) + unpack_sum(acc1);

        // Combine the two subs in this warp (lane r & r+16 hold same row)
        part += __shfl_down_sync(0xffffffffu, part, 16);
        if ((tid & 31) < 16) red_s[tid & 15][tid >> 5] = part;
        __syncthreads();

        // Warp-0 leaders: 8-way add, fast tanh, store h_{i+1}
        if (tid < RPC) {
            const float* rs = &red_s[tid][0];
            float4 u = *(const float4*)rs;
            float4 v = *(const float4*)(rs + 4);
            float s = ((u.x + u.y) + (u.z + u.w)) + ((v.x + v.y) + (v.z + v.w));
            float hv = fast_tanh(s + a_val + wb);
            g_Hst[(size_t)(i + 1) * HSZ + cta * RPC + tid] = hv;
        }
        __syncthreads();        // close the step: h stores + red_s reads done
        if (tid == 0) st_rel(&g_flags[cta * FPAD], (unsigned)(i + 1));
    }
}

// ---------------------------------------------------------------------------
// log_softmax over rows of Z [SEQLEN, OSZ], one warp per row
// ---------------------------------------------------------------------------
__global__ __launch_bounds__(128) void logsoftmax_k(
    const float* __restrict__ Z, float* __restrict__ Y)
{
    int warp = (blockIdx.x * blockDim.x + threadIdx.x) >> 5;
    int lane = threadIdx.x & 31;
    if (warp >= SEQLEN) return;
    const float* z = Z + (size_t)warp * OSZ;
    float v[16];
    float m = -INFINITY;
    #pragma unroll
    for (int j = 0; j < 16; ++j) {
        v[j] = z[lane + 32 * j];
        m = fmaxf(m, v[j]);
    }
    #pragma unroll
    for (int o = 16; o > 0; o >>= 1) m = fmaxf(m, __shfl_xor_sync(~0u, m, o));
    float s = 0.f;
    #pragma unroll
    for (int j = 0; j < 16; ++j) s += __expf(v[j] - m);
    #pragma unroll
    for (int o = 16; o > 0; o >>= 1) s += __shfl_xor_sync(~0u, s, o);
    float lse = m + __logf(s);
    float* y = Y + (size_t)warp * OSZ;
    #pragma unroll
    for (int j = 0; j < 16; ++j) y[lane + 32 * j] = v[j] - lse;
}

__global__ void copy_hfinal(float* __restrict__ out) {
    int i = blockIdx.x * blockDim.x + threadIdx.x;
    if (i < HSZ) out[i] = g_Hst[(size_t)SEQLEN * HSZ + i];
}

// ---------------------------------------------------------------------------
// kernel_launch
// Inputs: 0 input[8192,512] 1 hidden[1,2048] 2 U_w[2048,512] 3 U_b[2048]
//         4 W_w[2048,2048]  5 W_b[2048]      6 V_w[512,2048]  7 V_b[512]
// Output: y[8192,512] ++ h_final[2048]
// ---------------------------------------------------------------------------
extern "C" void kernel_launch(void* const* d_in, const int* in_sizes, int n_in,
                              void* d_out, int out_size)
{
    (void)in_sizes; (void)n_in; (void)out_size;
    const float* input  = (const float*)d_in[0];
    const float* hidden = (const float*)d_in[1];
    const float* U_w    = (const float*)d_in[2];
    const float* U_b    = (const float*)d_in[3];
    const float* W_w    = (const float*)d_in[4];
    const float* W_b    = (const float*)d_in[5];
    const float* V_w    = (const float*)d_in[6];
    const float* V_b    = (const float*)d_in[7];
    float* out = (float*)d_out;

    float *pA, *pH;
    cudaGetSymbolAddress((void**)&pA, g_A);
    cudaGetSymbolAddress((void**)&pH, g_Hst);

    // 1) reset flags + h_0
    init_k<<<16, 256>>>(hidden);

    // 2) A = X U^T + U_b : [8192,2048]
    sgemm_tn_bias<<<dim3(HSZ / 128, SEQLEN / 128), 256>>>(
        input, U_w, U_b, pA, SEQLEN, HSZ, INSZ);

    // 3) sequential recurrence -> g_Hst rows 1..8192
    rnn_recur<<<NCTA, 256>>>(W_w, W_b);

    // 4) Z = H V^T + V_b : [8192,512]  (reuse g_A as Z; H rows 1..8192)
    sgemm_tn_bias<<<dim3(OSZ / 128, SEQLEN / 128), 256>>>(
        pH + HSZ, V_w, V_b, pA, SEQLEN, OSZ, HSZ);

    // 5) y = log_softmax(Z) ; h_final
    logsoftmax_k<<<SEQLEN / 4, 128>>>(pA, out);
    copy_hfinal<<<8, 256>>>(out + (size_t)SEQLEN * OSZ);
}

// round 8
// speedup vs baseline: 3.3405x; 1.3110x over previous
#include <cuda_runtime.h>
#include <math.h>

// Problem dims
#define SEQLEN 8192
#define INSZ   512
#define HSZ    2048
#define OSZ    512

// Recurrence: 128 CTAs x 16 rows. Warp w (0..7) owns rows 2w, 2w+1.
// Lane l covers h/W elements 128j+4l..+3 for j=0..15 (coalesced float4).
#define NCTA 128
#define RPC  16

// Scratch (device globals: allocation-free rule)
__device__ float    g_A[(size_t)SEQLEN * HSZ];         // U x_t + U_b ; reused as Z
__device__ float    g_Hst[(size_t)(SEQLEN + 1) * HSZ]; // h_0 .. h_8192
__device__ unsigned g_ctr;                             // single release counter

// ---------------------------------------------------------------------------
// PTX helpers
// ---------------------------------------------------------------------------
static __device__ __forceinline__ unsigned ld_acq(const unsigned* p) {
    unsigned v;
    asm volatile("ld.acquire.gpu.global.u32 %0, [%1];" : "=r"(v) : "l"(p));
    return v;
}
static __device__ __forceinline__ void red_rel_add(unsigned* p, unsigned v) {
    asm volatile("red.release.gpu.global.add.u32 [%0], %1;" :: "l"(p), "r"(v));
}
// packed f32x2 FMA: acc.{lo,hi} += a*b  (Blackwell; 2x fp32 rate)
static __device__ __forceinline__ void fma2(unsigned long long& acc,
                                            float a0, float a1, float b0, float b1) {
    asm("{\n\t"
        ".reg .b64 ta, tb;\n\t"
        "mov.b64 ta, {%1, %2};\n\t"
        "mov.b64 tb, {%3, %4};\n\t"
        "fma.rn.f32x2 %0, ta, tb, %0;\n\t"
        "}"
        : "+l"(acc) : "f"(a0), "f"(a1), "f"(b0), "f"(b1));
}
static __device__ __forceinline__ float unpack_sum(unsigned long long acc) {
    float lo, hi;
    asm("mov.b64 {%0, %1}, %2;" : "=f"(lo), "=f"(hi) : "l"(acc));
    return lo + hi;
}
// tanh(x) = 1 - 2/(e^{2x}+1): MUFU ex2 + approx div (validated rel_err 1.1e-6)
static __device__ __forceinline__ float fast_tanh(float x) {
    float e = __expf(2.f * x);
    return 1.f - __fdividef(2.f, e + 1.f);
}

// ---------------------------------------------------------------------------
// Init: reset counter, load h_0
// ---------------------------------------------------------------------------
__global__ void init_k(const float* __restrict__ hidden) {
    int i = blockIdx.x * blockDim.x + threadIdx.x;
    if (i == 0) g_ctr = 0;
    if (i < HSZ) g_Hst[i] = hidden[i];
}

// ---------------------------------------------------------------------------
// SGEMM: C[M,N] = A[M,K] * B[N,K]^T + bias[N]   (row-major)
// ---------------------------------------------------------------------------
__global__ __launch_bounds__(256) void sgemm_tn_bias(
    const float* __restrict__ A, const float* __restrict__ B,
    const float* __restrict__ bias, float* __restrict__ C,
    int M, int N, int K)
{
    __shared__ float As[8][128];
    __shared__ float Bs[8][128];
    const int tid  = threadIdx.x;
    const int tx   = tid & 15;
    const int ty   = tid >> 4;
    const int lrow = tid >> 1;
    const int lcol = (tid & 1) * 4;

    const float* Ap = A + (size_t)(blockIdx.y * 128 + lrow) * K + lcol;
    const float* Bp = B + (size_t)(blockIdx.x * 128 + lrow) * K + lcol;

    float acc[8][8];
    #pragma unroll
    for (int i = 0; i < 8; ++i)
        #pragma unroll
        for (int j = 0; j < 8; ++j) acc[i][j] = 0.f;

    for (int k0 = 0; k0 < K; k0 += 8) {
        float4 a4 = *(const float4*)(Ap + k0);
        float4 b4 = *(const float4*)(Bp + k0);
        As[lcol + 0][lrow] = a4.x; As[lcol + 1][lrow] = a4.y;
        As[lcol + 2][lrow] = a4.z; As[lcol + 3][lrow] = a4.w;
        Bs[lcol + 0][lrow] = b4.x; Bs[lcol + 1][lrow] = b4.y;
        Bs[lcol + 2][lrow] = b4.z; Bs[lcol + 3][lrow] = b4.w;
        __syncthreads();
        #pragma unroll
        for (int k = 0; k < 8; ++k) {
            float ar[8], br[8];
            *(float4*)&ar[0] = *(const float4*)&As[k][ty * 8];
            *(float4*)&ar[4] = *(const float4*)&As[k][ty * 8 + 4];
            *(float4*)&br[0] = *(const float4*)&Bs[k][tx * 8];
            *(float4*)&br[4] = *(const float4*)&Bs[k][tx * 8 + 4];
            #pragma unroll
            for (int i = 0; i < 8; ++i)
                #pragma unroll
                for (int j = 0; j < 8; ++j)
                    acc[i][j] = fmaf(ar[i], br[j], acc[i][j]);
        }
        __syncthreads();
    }

    const int cm = blockIdx.y * 128 + ty * 8;
    const int cn = blockIdx.x * 128 + tx * 8;
    float bv[8];
    #pragma unroll
    for (int j = 0; j < 8; ++j) bv[j] = bias[cn + j];
    #pragma unroll
    for (int i = 0; i < 8; ++i) {
        float4 o0, o1;
        o0.x = acc[i][0] + bv[0]; o0.y = acc[i][1] + bv[1];
        o0.z = acc[i][2] + bv[2]; o0.w = acc[i][3] + bv[3];
        o1.x = acc[i][4] + bv[4]; o1.y = acc[i][5] + bv[5];
        o1.z = acc[i][6] + bv[6]; o1.w = acc[i][7] + bv[7];
        *(float4*)(C + (size_t)(cm + i) * N + cn)     = o0;
        *(float4*)(C + (size_t)(cm + i) * N + cn + 4) = o1;
    }
}

// ---------------------------------------------------------------------------
// Persistent recurrence: h_{i+1} = tanh(A[i] + W h_i + W_b)
// Warp w owns rows 2w/2w+1; h loads fully coalesced (warp covers the 8KB row);
// warp-local shfl reduction (no SMEM, no middle barrier). Sync skeleton = R2:
// tid0 polls single counter, one trailing __syncthreads, tid0 red.release.add.
// ---------------------------------------------------------------------------
__global__ __launch_bounds__(256, 1) void rnn_recur(
    const float* __restrict__ W, const float* __restrict__ Wb)
{
    const int tid  = threadIdx.x;
    const int cta  = blockIdx.x;
    const int warp = tid >> 5;     // 0..7
    const int lane = tid & 31;
    const int grow0 = cta * RPC + 2 * warp;      // this warp's first row

    // W slices in registers: rows grow0, grow0+1; lane l holds float4 j at
    // element offset 128j+4l (matches coalesced h load pattern).
    float4 w0[16], w1[16];
    {
        const float4* W0 = (const float4*)(W + (size_t)grow0 * HSZ);
        const float4* W1 = (const float4*)(W + (size_t)(grow0 + 1) * HSZ);
        #pragma unroll
        for (int j = 0; j < 16; ++j) { w0[j] = W0[32 * j + lane]; w1[j] = W1[32 * j + lane]; }
    }
    float2 wb = make_float2(0.f, 0.f);
    if (lane == 0) wb = *(const float2*)(Wb + grow0);

    for (int i = 0; i < SEQLEN; ++i) {
        // Prefetch A pair (flag-independent) — hides DRAM under the wait
        float2 av = make_float2(0.f, 0.f);
        if (lane == 0) av = *(const float2*)(g_A + (size_t)i * HSZ + grow0);

        // Wait for all CTAs to have published h_i (single-counter, tid0 only)
        if (i > 0) {
            if (tid == 0) {
                const unsigned target = (unsigned)i * NCTA;
                while (ld_acq(&g_ctr) < target) { }
            }
            __syncthreads();
        }

        // Coalesced h loads + dual-row packed FMA
        const float4* hp = (const float4*)(g_Hst + (size_t)i * HSZ);
        float4 hreg[16];
        #pragma unroll
        for (int j = 0; j < 16; ++j) hreg[j] = hp[32 * j + lane];
        unsigned long long a0 = 0ull, b0 = 0ull, a1 = 0ull, b1 = 0ull;
        #pragma unroll
        for (int j = 0; j < 16; ++j) {
            float4 h4 = hreg[j];
            fma2(a0, h4.x, h4.y, w0[j].x, w0[j].y);
            fma2(b0, h4.z, h4.w, w0[j].z, w0[j].w);
            fma2(a1, h4.x, h4.y, w1[j].x, w1[j].y);
            fma2(b1, h4.z, h4.w, w1[j].z, w1[j].w);
        }
        float p0 = unpack_sum(a0) + unpack_sum(b0);
        float p1 = unpack_sum(a1) + unpack_sum(b1);

        // Warp-local butterfly reduction: two independent chains, ILP overlap
        #pragma unroll
        for (int o = 16; o > 0; o >>= 1) {
            p0 += __shfl_xor_sync(0xffffffffu, p0, o);
            p1 += __shfl_xor_sync(0xffffffffu, p1, o);
        }

        // Lane 0 of each warp: tanh + store its row pair
        if (lane == 0) {
            float h0 = fast_tanh(p0 + av.x + wb.x);
            float h1 = fast_tanh(p1 + av.y + wb.y);
            *(float2*)(g_Hst + (size_t)(i + 1) * HSZ + grow0) = make_float2(h0, h1);
        }
        __syncthreads();          // all 16 rows of this CTA stored
        if (tid == 0) red_rel_add(&g_ctr, 1u);   // publish
    }
}

// ---------------------------------------------------------------------------
// log_softmax over rows of Z [SEQLEN, OSZ], one warp per row
// ---------------------------------------------------------------------------
__global__ __launch_bounds__(128) void logsoftmax_k(
    const float* __restrict__ Z, float* __restrict__ Y)
{
    int warp = (blockIdx.x * blockDim.x + threadIdx.x) >> 5;
    int lane = threadIdx.x & 31;
    if (warp >= SEQLEN) return;
    const float* z = Z + (size_t)warp * OSZ;
    float v[16];
    float m = -INFINITY;
    #pragma unroll
    for (int j = 0; j < 16; ++j) {
        v[j] = z[lane + 32 * j];
        m = fmaxf(m, v[j]);
    }
    #pragma unroll
    for (int o = 16; o > 0; o >>= 1) m = fmaxf(m, __shfl_xor_sync(~0u, m, o));
    float s = 0.f;
    #pragma unroll
    for (int j = 0; j < 16; ++j) s += __expf(v[j] - m);
    #pragma unroll
    for (int o = 16; o > 0; o >>= 1) s += __shfl_xor_sync(~0u, s, o);
    float lse = m + __logf(s);
    float* y = Y + (size_t)warp * OSZ;
    #pragma unroll
    for (int j = 0; j < 16; ++j) y[lane + 32 * j] = v[j] - lse;
}

__global__ void copy_hfinal(float* __restrict__ out) {
    int i = blockIdx.x * blockDim.x + threadIdx.x;
    if (i < HSZ) out[i] = g_Hst[(size_t)SEQLEN * HSZ + i];
}

// ---------------------------------------------------------------------------
// kernel_launch
// Inputs: 0 input[8192,512] 1 hidden[1,2048] 2 U_w[2048,512] 3 U_b[2048]
//         4 W_w[2048,2048]  5 W_b[2048]      6 V_w[512,2048]  7 V_b[512]
// Output: y[8192,512] ++ h_final[2048]
// ---------------------------------------------------------------------------
extern "C" void kernel_launch(void* const* d_in, const int* in_sizes, int n_in,
                              void* d_out, int out_size)
{
    (void)in_sizes; (void)n_in; (void)out_size;
    const float* input  = (const float*)d_in[0];
    const float* hidden = (const float*)d_in[1];
    const float* U_w    = (const float*)d_in[2];
    const float* U_b    = (const float*)d_in[3];
    const float* W_w    = (const float*)d_in[4];
    const float* W_b    = (const float*)d_in[5];
    const float* V_w    = (const float*)d_in[6];
    const float* V_b    = (const float*)d_in[7];
    float* out = (float*)d_out;

    float *pA, *pH;
    cudaGetSymbolAddress((void**)&pA, g_A);
    cudaGetSymbolAddress((void**)&pH, g_Hst);

    // 1) reset counter + h_0
    init_k<<<8, 256>>>(hidden);

    // 2) A = X U^T + U_b : [8192,2048]
    sgemm_tn_bias<<<dim3(HSZ / 128, SEQLEN / 128), 256>>>(
        input, U_w, U_b, pA, SEQLEN, HSZ, INSZ);

    // 3) sequential recurrence -> g_Hst rows 1..8192
    rnn_recur<<<NCTA, 256>>>(W_w, W_b);

    // 4) Z = H V^T + V_b : [8192,512]  (reuse g_A as Z; H rows 1..8192)
    sgemm_tn_bias<<<dim3(OSZ / 128, SEQLEN / 128), 256>>>(
        pH + HSZ, V_w, V_b, pA, SEQLEN, OSZ, HSZ);

    // 5) y = log_softmax(Z) ; h_final
    logsoftmax_k<<<SEQLEN / 4, 128>>>(pA, out);
    copy_hfinal<<<8, 256>>>(out + (size_t)SEQLEN * OSZ);
}